// round 7
// baseline (speedup 1.0000x reference)
#include <cuda_runtime.h>
#include <math.h>
#include <stdint.h>

#define Bsz 256
#define Tt  512
#define Hh  512
#define Oo  128
#define MHh 512
#define Ff  256
#define NB  148
#define TPB 256
#define PITCH 132

typedef unsigned long long ull;

#define PACK2(d, a) asm("mov.b64 %0, {%1, %1};" : "=l"(d) : "f"(a))
#define UNPACK2(lo, hi, v) asm("mov.b64 {%0, %1}, %2;" : "=f"(lo), "=f"(hi) : "l"(v))
#define FFMA2(acc, a, b) asm("fma.rn.f32x2 %0, %1, %2, %0;" : "+l"(acc) : "l"(a), "l"(b))

// ---------------- device scratch ----------------
__device__ float g_WihI [Oo * 4 * Hh];       // [k][j*4+g]
__device__ float g_WhhI [Hh * 4 * Hh];       // [k][2048]
__device__ float g_Wfold[Hh * 4 * Hh];       // [hid k][2048] = W2T1 @ WihI
__device__ float g_bgI  [4 * Hh];
__device__ float g_bgF  [4 * Hh];            // bgI + b2cat(p1) @ WihI
__device__ float g_Wf2hT[Ff * 2 * Hh];
__device__ float g_bhc  [2 * Hh];
__device__ float g_W12T [Hh * 2 * MHh];      // [k][p1|p2]
__device__ float g_b12  [2 * MHh];
__device__ float g_W2T1 [MHh * Oo];          // [k][n] = p1_W2[n][k]
__device__ float g_W2T2 [MHh * Oo];
__device__ float g_b2cat[2 * Oo];
__device__ float g_offW1T[Hh * MHh];

__device__ float g_hb[2][Bsz * Hh];
__device__ float g_cb[2][Bsz * Hh];
__device__ float g_gp[8][Bsz * 4 * Hh];               // PA K-split partials
__device__ float g_qpI[(size_t)Bsz * MHh * 8];        // q partials, interleaved [elt][8]
__device__ float g_hs [(size_t)Tt * Bsz * Hh];
__device__ float g_buf[(size_t)Tt * Bsz * 2 * MHh];   // post-loop hidden buffer
__device__ int   g_nt[Tt];
__device__ unsigned g_barCount;

// ---------------- preprocessing ----------------
__global__ void k_prep1(const float* __restrict__ W_ih, const float* __restrict__ W_hh,
                        const float* __restrict__ b_ih, const float* __restrict__ b_hh,
                        const float* __restrict__ W_f2h, const float* __restrict__ b_f2h) {
    int i = blockIdx.x * blockDim.x + threadIdx.x;
    if (i < Hh * 4 * Hh) {
        int k = i / 2048, n = i % 2048, j = n >> 2, g = n & 3;
        g_WhhI[i] = W_hh[(size_t)(g * Hh + j) * Hh + k];
    }
    if (i < Oo * 4 * Hh) {
        int k = i / 2048, n = i % 2048, j = n >> 2, g = n & 3;
        g_WihI[i] = W_ih[(size_t)(g * Hh + j) * Oo + k];
    }
    if (i < 4 * Hh) {
        int j = i >> 2, g = i & 3;
        g_bgI[i] = b_ih[g * Hh + j] + b_hh[g * Hh + j];
    }
    if (i < Ff * 2 * Hh) {
        int k = i / (2 * Hh), j = i % (2 * Hh);
        int src = (j < Hh) ? 2 * j : 2 * (j - Hh) + 1;
        g_Wf2hT[i] = W_f2h[(size_t)src * Ff + k];
    }
    if (i < 2 * Hh) {
        int src = (i < Hh) ? 2 * i : 2 * (i - Hh) + 1;
        g_bhc[i] = b_f2h[src];
    }
}

__global__ void k_prep2(const float* __restrict__ p1_W1, const float* __restrict__ p2_W1,
                        const float* __restrict__ p1_b1, const float* __restrict__ p2_b1,
                        const float* __restrict__ p1_W2, const float* __restrict__ p2_W2,
                        const float* __restrict__ p1_b2, const float* __restrict__ p2_b2,
                        const float* __restrict__ off_W1, const int* __restrict__ lengths) {
    int i = blockIdx.x * blockDim.x + threadIdx.x;
    if (i < Hh * 2 * MHh) {
        int k = i / (2 * MHh), n = i % (2 * MHh);
        g_W12T[i] = (n < MHh) ? p1_W1[(size_t)n * Hh + k]
                              : p2_W1[(size_t)(n - MHh) * Hh + k];
    }
    if (i < MHh * Oo) {
        int k = i >> 7, n = i & 127;
        g_W2T1[i] = p1_W2[(size_t)n * MHh + k];
        g_W2T2[i] = p2_W2[(size_t)n * MHh + k];
    }
    if (i < MHh * Hh) {
        int r = i / Hh, c = i % Hh;
        g_offW1T[(size_t)c * MHh + r] = off_W1[i];
    }
    if (i < 2 * MHh) g_b12[i] = (i < MHh) ? p1_b1[i] : p2_b1[i - MHh];
    if (i < 2 * Oo)  g_b2cat[i] = (i < Oo) ? p1_b2[i] : p2_b2[i - Oo];
    if (i == 0) g_barCount = 0u;
    if (i < Tt) {
        int c = 0;
        for (int b = 0; b < Bsz; ++b) c += (lengths[b] > i) ? 1 : 0;
        g_nt[i] = c;
    }
}

__global__ void k_bgF() {
    int n = blockIdx.x * blockDim.x + threadIdx.x;
    if (n >= 4 * Hh) return;
    float v = g_bgI[n];
    for (int k = 0; k < Oo; ++k) v += g_b2cat[k] * g_WihI[k * 2048 + n];
    g_bgF[n] = v;
}

// ---------------- 128x128 f32x2 tile engine ----------------
template <class AF, class BF>
__device__ __forceinline__ void tile128(float (&o)[8][8], int ksteps, AF af, BF bf,
                                        float* As, float* Bs) {
    const int tid = threadIdx.x;
    const int tx = tid & 15, ty = tid >> 4;
    const int ak = tid & 15, am = tid >> 4;
    const int bk = tid >> 7, bn = tid & 127;

    float ra[8], rb[8];
#pragma unroll
    for (int i = 0; i < 8; ++i) ra[i] = af(am + i * 16, ak);
#pragma unroll
    for (int i = 0; i < 8; ++i) rb[i] = bf(bk + i * 2, bn);

    ull acc[8][4];
#pragma unroll
    for (int i = 0; i < 8; ++i)
#pragma unroll
        for (int j = 0; j < 4; ++j) acc[i][j] = 0ull;

    for (int kt = 0; kt < ksteps; ++kt) {
#pragma unroll
        for (int i = 0; i < 8; ++i) As[ak * PITCH + am + i * 16] = ra[i];
#pragma unroll
        for (int i = 0; i < 8; ++i) Bs[(bk + i * 2) * PITCH + bn] = rb[i];
        __syncthreads();
        if (kt + 1 < ksteps) {
            const int k1 = (kt + 1) * 16;
#pragma unroll
            for (int i = 0; i < 8; ++i) ra[i] = af(am + i * 16, k1 + ak);
#pragma unroll
            for (int i = 0; i < 8; ++i) rb[i] = bf(k1 + bk + i * 2, bn);
        }
#pragma unroll
        for (int k = 0; k < 16; ++k) {
            const float4 a01 = *(const float4*)&As[k * PITCH + ty * 8];
            const float4 a23 = *(const float4*)&As[k * PITCH + ty * 8 + 4];
            const ulonglong2 b01 = *(const ulonglong2*)&Bs[k * PITCH + tx * 8];
            const ulonglong2 b23 = *(const ulonglong2*)&Bs[k * PITCH + tx * 8 + 4];
            const ull bv0 = b01.x, bv1 = b01.y, bv2 = b23.x, bv3 = b23.y;
            const float av[8] = {a01.x, a01.y, a01.z, a01.w, a23.x, a23.y, a23.z, a23.w};
#pragma unroll
            for (int i = 0; i < 8; ++i) {
                ull ad;
                PACK2(ad, av[i]);
                FFMA2(acc[i][0], ad, bv0);
                FFMA2(acc[i][1], ad, bv1);
                FFMA2(acc[i][2], ad, bv2);
                FFMA2(acc[i][3], ad, bv3);
            }
        }
        __syncthreads();
    }
#pragma unroll
    for (int i = 0; i < 8; ++i)
#pragma unroll
        for (int j = 0; j < 4; ++j) {
            float lo, hi;
            UNPACK2(lo, hi, acc[i][j]);
            o[i][j * 2] = lo;
            o[i][j * 2 + 1] = hi;
        }
}

// ---------------- generic GEMM (prep/init/post-loop) ----------------
// MODE 0: C = acc+bias ; 1: tanh ; 2: h/c split init ; 3: plain dual-store (C, C2)
template <int MODE>
__global__ void __launch_bounds__(256, 1)
gemmG(const float* __restrict__ A, int lda, const int* __restrict__ aidx,
      const float* __restrict__ Bm, int ldb, const float* __restrict__ bias,
      float* __restrict__ C, float* __restrict__ C2, int M, int N, int K) {
    __shared__ __align__(16) float As[16 * PITCH];
    __shared__ __align__(16) float Bs[16 * PITCH];
    const int n0 = blockIdx.x * 128;
    const int m0 = blockIdx.y * 128;
    const int tx = threadIdx.x & 15, ty = threadIdx.x >> 4;

    float o[8][8];
    auto af = [&](int ml, int kk) -> float {
        int m = m0 + ml;
        if (m >= M) return 0.f;
        int row = aidx ? aidx[m] : m;
        return A[(size_t)row * lda + kk];
    };
    auto bf = [&](int kk, int nl) -> float {
        return Bm[(size_t)kk * ldb + n0 + nl];
    };
    tile128(o, K / 16, af, bf, As, Bs);

#pragma unroll
    for (int i = 0; i < 8; ++i) {
        int m = m0 + ty * 8 + i;
        if (m >= M) continue;
#pragma unroll
        for (int j = 0; j < 8; ++j) {
            int n = n0 + tx * 8 + j;
            float r = o[i][j] + (bias ? bias[n] : 0.f);
            if (MODE == 1) r = tanhf(r);
            if (MODE == 2) {
                if (n < Hh) g_hb[0][m * Hh + n] = r;
                else        g_cb[0][m * Hh + (n - Hh)] = r;
            } else {
                C[(size_t)m * N + n] = r;
                if (MODE == 3) C2[(size_t)m * N + n] = r;
            }
        }
    }
}

// ---------------- persistent scan ----------------
__device__ __forceinline__ float sigm(float x) { return 1.f / (1.f + expf(-x)); }

__device__ __forceinline__ void gridsync(unsigned& phase) {
    __syncthreads();
    if (threadIdx.x == 0) {
        __threadfence();
        phase += 1u;
        const unsigned target = phase * NB;
        atomicAdd(&g_barCount, 1u);
        while (*((volatile unsigned*)&g_barCount) < target) { __nanosleep(64); }
        __threadfence();
    }
    __syncthreads();
}

__global__ void __launch_bounds__(TPB, 1) persistent_scan() {
    __shared__ __align__(16) float As[16 * PITCH];
    __shared__ __align__(16) float Bs[16 * PITCH];
    const int bid = blockIdx.x;
    const int tid = threadIdx.x;
    const int tx = tid & 15, ty = tid >> 4;
    unsigned phase = 0;

    for (int t = 0; t < Tt; ++t) {
        const int nt = g_nt[t];
        const int mt2 = (nt + 127) >> 7;              // m-tiles of 128
        const int rd = t & 1, wr = rd ^ 1;
        const float* __restrict__ hR = g_hb[rd];
        float* __restrict__ hW = g_hb[wr];
        const float* __restrict__ cR = g_cb[rd];
        float* __restrict__ cW = g_cb[wr];
        const int kbase = (t > 0) ? 0 : 512;          // t=0: h-part only
        const int Ktot = 1024 - kbase;
        const int Ka = Ktot >> 3;                     // ks_a = 8

        // ---- P0: gates partials = tanh(q+b1)@Wfold + h@WhhI (K-split 8) ----
        const int tilesA = mt2 * 16 * 8;
        for (int tile = bid; tile < tilesA; tile += NB) {
            const int s = tile & 7;
            const int u = tile >> 3;
            const int n0 = (u & 15) << 7;
            const int m0 = (u >> 4) << 7;
            const int k0 = kbase + s * Ka;

            auto af = [&](int ml, int kk) -> float {
                int gk = k0 + kk;
                int m = m0 + ml;
                if (gk < 512) {
                    const float* q = &g_qpI[((size_t)m * MHh + gk) * 8];
                    float4 q0 = *(const float4*)q;
                    float4 q1 = *(const float4*)(q + 4);
                    float v = q0.x + q0.y + q0.z + q0.w +
                              q1.x + q1.y + q1.z + q1.w + g_b12[gk];
                    return tanhf(v);
                }
                return hR[m * Hh + (gk - 512)];
            };
            auto bf = [&](int kk, int nl) -> float {
                int gk = k0 + kk;
                return (gk < 512) ? g_Wfold[(size_t)gk * 2048 + n0 + nl]
                                  : g_WhhI[(size_t)(gk - 512) * 2048 + n0 + nl];
            };
            float o[8][8];
            tile128(o, Ka / 16, af, bf, As, Bs);

            float* __restrict__ gout = g_gp[s];
#pragma unroll
            for (int i = 0; i < 8; ++i) {
                float* dst = &gout[(m0 + ty * 8 + i) * 2048 + n0 + tx * 8];
                *(float4*)dst = make_float4(o[i][0], o[i][1], o[i][2], o[i][3]);
                *(float4*)(dst + 4) = make_float4(o[i][4], o[i][5], o[i][6], o[i][7]);
            }
        }
        gridsync(phase);

        // ---- P1: LSTM combine (sum 8 partials + bias) ----
        {
            const float* __restrict__ bgSel = (t > 0) ? g_bgF : g_bgI;
            const int total = mt2 * 128 * Hh;
            for (int e = bid * TPB + tid; e < total; e += NB * TPB) {
                int m = e >> 9, j = e & (Hh - 1);
                if (m < nt) {
                    float4 gs = make_float4(0.f, 0.f, 0.f, 0.f);
#pragma unroll
                    for (int s = 0; s < 8; ++s) {
                        float4 gp = *(const float4*)&g_gp[s][m * 2048 + j * 4];
                        gs.x += gp.x; gs.y += gp.y; gs.z += gp.z; gs.w += gp.w;
                    }
                    float4 bg = *(const float4*)&bgSel[j * 4];
                    float cn = sigm(gs.y + bg.y) * cR[m * Hh + j] +
                               sigm(gs.x + bg.x) * tanhf(gs.z + bg.z);
                    float hn = sigm(gs.w + bg.w) * tanhf(cn);
                    cW[m * Hh + j] = cn;
                    hW[m * Hh + j] = hn;
                    g_hs[((size_t)t * Bsz + m) * Hh + j] = hn;
                }
            }
        }
        gridsync(phase);

        // ---- P2: q partials = h @ W12T[:, 0:512] (K-split 8, interleaved out) ----
        const int tilesB = mt2 * 4 * 8;
        for (int tile = bid; tile < tilesB; tile += NB) {
            const int s = tile & 7;
            const int u = tile >> 3;
            const int n0 = (u & 3) << 7;
            const int m0 = (u >> 2) << 7;
            const int k0 = s * 64;

            auto af = [&](int ml, int kk) -> float {
                return hW[(m0 + ml) * Hh + k0 + kk];
            };
            auto bf = [&](int kk, int nl) -> float {
                return g_W12T[(size_t)(k0 + kk) * 1024 + n0 + nl];
            };
            float o[8][8];
            tile128(o, 4, af, bf, As, Bs);
#pragma unroll
            for (int i = 0; i < 8; ++i) {
                int m = m0 + ty * 8 + i;
#pragma unroll
                for (int j = 0; j < 8; ++j)
                    g_qpI[((size_t)m * MHh + n0 + tx * 8 + j) * 8 + s] = o[i][j];
            }
        }
        gridsync(phase);
    }
}

// ---------------- final stage ----------------
__global__ void offsets_kernel(const float* __restrict__ offW2, const float* __restrict__ offb2,
                               float* __restrict__ out_off, int Np) {
    int warp = (blockIdx.x * blockDim.x + threadIdx.x) >> 5;
    int lane = threadIdx.x & 31;
    if (warp >= Np) return;
    const float* row = g_buf + (size_t)warp * MHh;
    float s = 0.f;
#pragma unroll
    for (int k = lane; k < MHh; k += 32) s += row[k] * offW2[k];
#pragma unroll
    for (int o = 16; o; o >>= 1) s += __shfl_xor_sync(0xFFFFFFFFu, s, o);
    if (lane == 0) out_off[warp] = s + offb2[0];
}

// ---------------- host ----------------
static float* gsymf(const void* symbol) {
    void* p = nullptr;
    cudaGetSymbolAddress(&p, symbol);
    return (float*)p;
}

extern "C" void kernel_launch(void* const* d_in, const int* in_sizes, int n_in,
                              void* d_out, int out_size) {
    const float* features = (const float*)d_in[0];
    const float* W_f2h    = (const float*)d_in[1];
    const float* b_f2h    = (const float*)d_in[2];
    const float* W_ih     = (const float*)d_in[3];
    const float* W_hh     = (const float*)d_in[4];
    const float* b_ih     = (const float*)d_in[5];
    const float* b_hh     = (const float*)d_in[6];
    const float* p1_W1    = (const float*)d_in[7];
    const float* p1_b1    = (const float*)d_in[8];
    const float* p1_W2    = (const float*)d_in[9];
    const float* p1_b2    = (const float*)d_in[10];
    const float* p2_W1    = (const float*)d_in[11];
    const float* p2_b1    = (const float*)d_in[12];
    const float* p2_W2    = (const float*)d_in[13];
    const float* p2_b2    = (const float*)d_in[14];
    const float* off_W1   = (const float*)d_in[15];
    const float* off_b1   = (const float*)d_in[16];
    const float* off_W2   = (const float*)d_in[17];
    const float* off_b2   = (const float*)d_in[18];
    const int*   lengths  = (const int*)d_in[19];
    const int*   pack_idx = (const int*)d_in[20];
    float* out = (float*)d_out;
    const int Np = in_sizes[20];
    const size_t NO = (size_t)Np * Oo;
    const unsigned mT = (unsigned)((Np + 127) / 128);

    float* p_WihI   = gsymf(g_WihI);
    float* p_Wfold  = gsymf(g_Wfold);
    float* p_Wf2hT  = gsymf(g_Wf2hT);
    float* p_bhc    = gsymf(g_bhc);
    float* p_W12T   = gsymf(g_W12T);
    float* p_b12    = gsymf(g_b12);
    float* p_W2T1   = gsymf(g_W2T1);
    float* p_W2T2   = gsymf(g_W2T2);
    float* p_b2cat  = gsymf(g_b2cat);
    float* p_offW1T = gsymf(g_offW1T);
    float* p_hs     = gsymf(g_hs);
    float* p_buf    = gsymf(g_buf);

    auto blocks = [](long long n) { return (unsigned)((n + 255) / 256); };

    // prep
    k_prep1<<<blocks(4LL * Hh * Hh), TPB>>>(W_ih, W_hh, b_ih, b_hh, W_f2h, b_f2h);
    k_prep2<<<blocks((long long)Hh * 2 * MHh), TPB>>>(p1_W1, p2_W1, p1_b1, p2_b1,
                                                      p1_W2, p2_W2, p1_b2, p2_b2,
                                                      off_W1, lengths);
    k_bgF<<<blocks(4 * Hh), TPB>>>();
    // Wfold = W2T1 @ WihI  (512 x 2048, K=128)
    gemmG<0><<<dim3(16, 4), TPB>>>(p_W2T1, Oo, nullptr, p_WihI, 2048, nullptr,
                                   p_Wfold, nullptr, Hh, 4 * Hh, Oo);
    // init h0/c0 = features @ Wf2hT + bhc (split epilogue)
    gemmG<2><<<dim3(8, 2), TPB>>>(features, Ff, nullptr, p_Wf2hT, 2 * Hh, p_bhc,
                                  nullptr, nullptr, Bsz, 2 * Hh, Ff);

    // the scan: 3 grid-syncs/step, p1 folded into PA
    persistent_scan<<<NB, TPB>>>();

    // post-loop over packed rows:
    // hid12 = tanh(h_packed @ W12T + b12)  -> g_buf [Np x 1024]
    gemmG<1><<<dim3(8, mT), TPB>>>(p_hs, Hh, pack_idx, p_W12T, 1024, p_b12,
                                   p_buf, nullptr, Np, 1024, Hh);
    // flat_p1 (+ flat_out copy) = hid12[:, :512] @ W2T1 + b2
    gemmG<3><<<dim3(1, mT), TPB>>>(p_buf, 1024, nullptr, p_W2T1, Oo, p_b2cat,
                                   out, out + 2 * NO + Np, Np, Oo, MHh);
    // flat_p2 = hid12[:, 512:] @ W2T2 + b2'
    gemmG<0><<<dim3(1, mT), TPB>>>(p_buf + MHh, 1024, nullptr, p_W2T2, Oo, p_b2cat + Oo,
                                   out + NO, nullptr, Np, Oo, MHh);
    // offsets hidden = tanh(h_packed @ offW1T + off_b1) -> g_buf [Np x 512] (reuse)
    gemmG<1><<<dim3(4, mT), TPB>>>(p_hs, Hh, pack_idx, p_offW1T, MHh, off_b1,
                                   p_buf, nullptr, Np, MHh, Hh);
    offsets_kernel<<<(Np + 7) / 8, TPB>>>(off_W2, off_b2, out + 2 * NO, Np);
}

// round 8
// speedup vs baseline: 1.7254x; 1.7254x over previous
#include <cuda_runtime.h>
#include <math.h>
#include <stdint.h>

#define Bsz 256
#define Tt  512
#define Hh  512
#define Oo  128
#define MHh 512
#define Ff  256
#define NB  296
#define TPB 256
#define KSC 4      // P3 K-split factor
#define PAP 68     // A-tile smem pitch (floats): conflict-free float4 stores

// ---------------- device scratch ----------------
__device__ float g_WihI [Oo * 4 * Hh];      // [k][j*4+g]
__device__ float g_WhhI [Hh * 4 * Hh];
__device__ float g_bgI  [4 * Hh];
__device__ float g_Wf2hT[Ff * 2 * Hh];
__device__ float g_bhc  [2 * Hh];
__device__ float g_W12T [Hh * 2 * MHh];     // [k][p1|p2]
__device__ float g_b12  [2 * MHh];
__device__ float g_W2T1 [MHh * Oo];
__device__ float g_W2T2 [MHh * Oo];
__device__ float g_b2cat[2 * Oo];
__device__ float g_offW1T[Hh * MHh];

__device__ float g_hb[2][Bsz * Hh];
__device__ float g_cb[2][Bsz * Hh];
__device__ float g_gp[8][Bsz * 4 * Hh];              // PA partials (ks_a<=8)
__device__ float g_qp[8][Bsz * MHh];                 // P2 partials (ks_b=8)
__device__ float g_rp[KSC][(size_t)Tt * Bsz * Oo];   // P3 partials per t
__device__ float g_hs [(size_t)Tt * Bsz * Hh];
__device__ float g_buf[(size_t)Tt * Bsz * MHh];
__device__ int   g_nt[Tt];
__device__ unsigned g_barCount;

// ---------------- preprocessing (2 launches) ----------------
__global__ void k_prepA(const float* __restrict__ W_ih, const float* __restrict__ W_hh,
                        const float* __restrict__ b_ih, const float* __restrict__ b_hh,
                        const float* __restrict__ W_f2h, const float* __restrict__ b_f2h) {
    int i = blockIdx.x * blockDim.x + threadIdx.x;
    if (i < Hh * 4 * Hh) {
        int k = i / 2048, n = i % 2048, j = n >> 2, g = n & 3;
        g_WhhI[i] = W_hh[(size_t)(g * Hh + j) * Hh + k];
    }
    if (i < Oo * 4 * Hh) {
        int k = i / 2048, n = i % 2048, j = n >> 2, g = n & 3;
        g_WihI[i] = W_ih[(size_t)(g * Hh + j) * Oo + k];
    }
    if (i < 4 * Hh) {
        int j = i >> 2, g = i & 3;
        g_bgI[i] = b_ih[g * Hh + j] + b_hh[g * Hh + j];
    }
    if (i < Ff * 2 * Hh) {
        int k = i / (2 * Hh), j = i % (2 * Hh);
        int src = (j < Hh) ? 2 * j : 2 * (j - Hh) + 1;
        g_Wf2hT[i] = W_f2h[(size_t)src * Ff + k];
    }
    if (i < 2 * Hh) {
        int src = (i < Hh) ? 2 * i : 2 * (i - Hh) + 1;
        g_bhc[i] = b_f2h[src];
    }
}

__global__ void k_prepB(const float* __restrict__ p1_W1, const float* __restrict__ p2_W1,
                        const float* __restrict__ p1_b1, const float* __restrict__ p2_b1,
                        const float* __restrict__ p1_W2, const float* __restrict__ p2_W2,
                        const float* __restrict__ p1_b2, const float* __restrict__ p2_b2,
                        const float* __restrict__ off_W1, const int* __restrict__ lengths) {
    int i = blockIdx.x * blockDim.x + threadIdx.x;
    if (i < Hh * 2 * MHh) {
        int k = i / (2 * MHh), n = i % (2 * MHh);
        g_W12T[i] = (n < MHh) ? p1_W1[(size_t)n * Hh + k]
                              : p2_W1[(size_t)(n - MHh) * Hh + k];
    }
    if (i < MHh * Oo) {
        int k = i >> 7, n = i & 127;
        g_W2T1[i] = p1_W2[(size_t)n * MHh + k];
        g_W2T2[i] = p2_W2[(size_t)n * MHh + k];
    }
    if (i < MHh * Hh) {
        int r = i / Hh, c = i % Hh;
        g_offW1T[(size_t)c * MHh + r] = off_W1[i];
    }
    if (i < 2 * MHh) g_b12[i] = (i < MHh) ? p1_b1[i] : p2_b1[i - MHh];
    if (i < 2 * Oo)  g_b2cat[i] = (i < Oo) ? p1_b2[i] : p2_b2[i - Oo];
    if (i == 0) g_barCount = 0u;
    if (i < Tt) {
        int c = 0;
        for (int b = 0; b < Bsz; ++b) c += (lengths[b] > i) ? 1 : 0;
        g_nt[i] = c;
    }
}

// ---------------- 64x64 MAC core (conflict-free A stores) ----------------
// A fragment: thread (tx=k, ty) holds m = ty*4+i; stored as one float4.
template <class AF, class BF>
__device__ __forceinline__ void mac64(float (&acc)[4][4], int K, AF af, BF bf,
                                      float* As, float* Bs) {
    const int tid = threadIdx.x;
    const int tx = tid & 15, ty = tid >> 4;
    const int bk = tid >> 6, bn = tid & 63;
    float ra[4], rb[4];
#pragma unroll
    for (int i = 0; i < 4; ++i) ra[i] = af(ty * 4 + i, tx);
#pragma unroll
    for (int i = 0; i < 4; ++i) rb[i] = bf(bk + i * 4, bn);

    for (int kt = 0; kt < K; kt += 16) {
        *(float4*)&As[tx * PAP + ty * 4] = make_float4(ra[0], ra[1], ra[2], ra[3]);
#pragma unroll
        for (int i = 0; i < 4; ++i) Bs[(bk + i * 4) * 64 + bn] = rb[i];
        __syncthreads();
        if (kt + 16 < K) {
#pragma unroll
            for (int i = 0; i < 4; ++i) ra[i] = af(ty * 4 + i, kt + 16 + tx);
#pragma unroll
            for (int i = 0; i < 4; ++i) rb[i] = bf(kt + 16 + bk + i * 4, bn);
        }
#pragma unroll
        for (int k = 0; k < 16; ++k) {
            float4 a4 = *(const float4*)&As[k * PAP + ty * 4];
            float4 b4 = *(const float4*)&Bs[k * 64 + tx * 4];
            float av[4] = {a4.x, a4.y, a4.z, a4.w};
            float bv[4] = {b4.x, b4.y, b4.z, b4.w};
#pragma unroll
            for (int i = 0; i < 4; ++i)
#pragma unroll
                for (int j = 0; j < 4; ++j) acc[i][j] += av[i] * bv[j];
        }
        __syncthreads();
    }
}

// ---------------- generic GEMM ----------------
// MODE 0: C=acc+bias ; 1: tanh ; 2: h/c split init ; 3: dual store (C, C2)
template <int MODE>
__global__ void __launch_bounds__(256)
gemmG(const float* __restrict__ A, int lda, const int* __restrict__ aidx,
      const float* __restrict__ Bm, int ldb, const float* __restrict__ bias,
      float* __restrict__ C, float* __restrict__ C2, int M, int N, int K) {
    __shared__ __align__(16) float As[16 * PAP];
    __shared__ __align__(16) float Bs[16 * 64];
    const int n0 = blockIdx.x * 64;
    const int m0 = blockIdx.y * 64;
    const int tx = threadIdx.x & 15, ty = threadIdx.x >> 4;

    float acc[4][4];
#pragma unroll
    for (int i = 0; i < 4; ++i)
#pragma unroll
        for (int j = 0; j < 4; ++j) acc[i][j] = 0.f;

    auto af = [&](int ml, int kk) -> float {
        int m = m0 + ml;
        if (m >= M) return 0.f;
        int row = aidx ? aidx[m] : m;
        return A[(size_t)row * lda + kk];
    };
    auto bf = [&](int kk, int nl) -> float {
        return Bm[(size_t)kk * ldb + n0 + nl];
    };
    mac64(acc, K, af, bf, As, Bs);

#pragma unroll
    for (int i = 0; i < 4; ++i) {
        int m = m0 + ty * 4 + i;
        if (m >= M) continue;
#pragma unroll
        for (int j = 0; j < 4; ++j) {
            int n = n0 + tx * 4 + j;
            float r = acc[i][j] + (bias ? bias[n] : 0.f);
            if (MODE == 1) r = tanhf(r);
            if (MODE == 2) {
                if (n < Hh) g_hb[0][m * Hh + n] = r;
                else        g_cb[0][m * Hh + (n - Hh)] = r;
            } else {
                C[(size_t)m * N + n] = r;
                if (MODE == 3) C2[(size_t)m * N + n] = r;
            }
        }
    }
}

// ---------------- persistent scan ----------------
__device__ __forceinline__ float sigm(float x) { return 1.f / (1.f + expf(-x)); }

__device__ __forceinline__ void gridsync(unsigned& phase) {
    __syncthreads();
    if (threadIdx.x == 0) {
        __threadfence();
        phase += 1u;
        const unsigned target = phase * NB;
        atomicAdd(&g_barCount, 1u);
        while (*((volatile unsigned*)&g_barCount) < target) { __nanosleep(64); }
        __threadfence();
    }
    __syncthreads();
}

__global__ void __launch_bounds__(TPB, 2) persistent_scan() {
    __shared__ __align__(16) float As[16 * PAP];
    __shared__ __align__(16) float Bs[16 * 64];
    const int bid = blockIdx.x;
    const int tid = threadIdx.x;
    const int tx = tid & 15, ty = tid >> 4;
    unsigned phase = 0;

    for (int t = 0; t < Tt; ++t) {
        const int nt = g_nt[t];
        const int mt = (nt + 63) >> 6;
        const int rd = t & 1, wr = rd ^ 1;
        const float* __restrict__ hR = g_hb[rd];
        float* __restrict__ hW = g_hb[wr];
        const float* __restrict__ cR = g_cb[rd];
        float* __restrict__ cW = g_cb[wr];
        const bool hasx = (t > 0);
        const int xoff = hasx ? 128 : 0;
        const int kspace = Hh + xoff;                 // 640 or 512
        const int ks_a = (mt >= 3) ? 2 : (mt == 2 ? 4 : 8);
        const int Ka = kspace / ks_a;
        const size_t rbase = hasx ? (size_t)(t - 1) * Bsz * Oo : 0;

        // ---- P0: gates partials = x@WihI + h@WhhI (K-split) ----
        const int tilesA = mt * 32 * ks_a;
        for (int tile = bid; tile < tilesA; tile += NB) {
            const int s  = tile % ks_a;
            const int u  = tile / ks_a;
            const int n0 = (u & 31) << 6;
            const int m0 = (u >> 5) << 6;
            const int k0 = s * Ka;
            float acc[4][4];
#pragma unroll
            for (int i = 0; i < 4; ++i)
#pragma unroll
                for (int j = 0; j < 4; ++j) acc[i][j] = 0.f;

            auto af = [&](int ml, int kk) -> float {
                int gk = k0 + kk;
                int m = m0 + ml;
                if (hasx && gk < Oo) {
                    size_t ix = rbase + (size_t)m * Oo + gk;
                    float v = g_b2cat[gk];
#pragma unroll
                    for (int sc = 0; sc < KSC; ++sc) v += g_rp[sc][ix];
                    return v;
                }
                return hR[m * Hh + gk - xoff];
            };
            auto bf = [&](int kk, int nl) -> float {
                int gk = k0 + kk;
                return (hasx && gk < Oo) ? g_WihI[gk * 2048 + n0 + nl]
                                         : g_WhhI[(size_t)(gk - xoff) * 2048 + n0 + nl];
            };
            mac64(acc, Ka, af, bf, As, Bs);

            float* __restrict__ gout = g_gp[s];
#pragma unroll
            for (int i = 0; i < 4; ++i) {
                int m = m0 + ty * 4 + i;
#pragma unroll
                for (int j = 0; j < 4; ++j)
                    gout[m * 2048 + n0 + tx * 4 + j] = acc[i][j];
            }
        }
        gridsync(phase);

        // ---- P1: LSTM combine ----
        {
            const int total = mt * 64 * Hh;
            for (int e = bid * TPB + tid; e < total; e += NB * TPB) {
                int m = e >> 9, j = e & (Hh - 1);
                if (m < nt) {
                    float4 gs = make_float4(0.f, 0.f, 0.f, 0.f);
                    for (int s = 0; s < ks_a; ++s) {
                        float4 gp = *(const float4*)&g_gp[s][m * 2048 + j * 4];
                        gs.x += gp.x; gs.y += gp.y; gs.z += gp.z; gs.w += gp.w;
                    }
                    float4 bg = *(const float4*)&g_bgI[j * 4];
                    float cn = sigm(gs.y + bg.y) * cR[m * Hh + j] +
                               sigm(gs.x + bg.x) * tanhf(gs.z + bg.z);
                    float hn = sigm(gs.w + bg.w) * tanhf(cn);
                    cW[m * Hh + j] = cn;
                    hW[m * Hh + j] = hn;
                    g_hs[((size_t)t * Bsz + m) * Hh + j] = hn;
                }
            }
            gridsync(phase);
        }

        // ---- P2: q partials = h_t @ W12T[:, 0:512], K-split 8 ----
        const int Kb = MHh / 8;   // 64
        const int tilesB = mt * 8 * 8;
        for (int tile = bid; tile < tilesB; tile += NB) {
            const int s  = tile & 7;
            const int u  = tile >> 3;
            const int n0 = (u & 7) << 6;
            const int m0 = (u >> 3) << 6;
            const int k0 = s * Kb;
            float* __restrict__ qout = g_qp[s];
            float acc[4][4];
#pragma unroll
            for (int i = 0; i < 4; ++i)
#pragma unroll
                for (int j = 0; j < 4; ++j) acc[i][j] = 0.f;
            auto af = [&](int ml, int kk) -> float { return hW[(m0 + ml) * Hh + k0 + kk]; };
            auto bf = [&](int kk, int nl) -> float {
                return g_W12T[(size_t)(k0 + kk) * 1024 + n0 + nl];
            };
            mac64(acc, Kb, af, bf, As, Bs);
#pragma unroll
            for (int i = 0; i < 4; ++i) {
                int m = m0 + ty * 4 + i;
#pragma unroll
                for (int j = 0; j < 4; ++j)
                    qout[m * MHh + n0 + tx * 4 + j] = acc[i][j];
            }
        }
        gridsync(phase);

        // ---- P3: p1 partials = tanh(sum q + b12) @ W2T1, K-split 4 ----
        const int Kc = MHh / KSC;    // 128
        const int tilesC = mt * 2 * KSC;
        for (int tile = bid; tile < tilesC; tile += NB) {
            const int s  = tile % KSC;
            const int u  = tile / KSC;
            const int n0 = (u & 1) << 6;
            const int m0 = (u >> 1) << 6;
            const int k0 = s * Kc;
            float* __restrict__ rout = g_rp[s] + (size_t)t * Bsz * Oo;
            float acc[4][4];
#pragma unroll
            for (int i = 0; i < 4; ++i)
#pragma unroll
                for (int j = 0; j < 4; ++j) acc[i][j] = 0.f;
            auto af = [&](int ml, int kk) -> float {
                int k = k0 + kk;
                float v = g_b12[k];
#pragma unroll
                for (int s2 = 0; s2 < 8; ++s2) v += g_qp[s2][(m0 + ml) * MHh + k];
                return tanhf(v);
            };
            auto bf = [&](int kk, int nl) -> float { return g_W2T1[(k0 + kk) * Oo + n0 + nl]; };
            mac64(acc, Kc, af, bf, As, Bs);
#pragma unroll
            for (int i = 0; i < 4; ++i) {
                int m = m0 + ty * 4 + i;
#pragma unroll
                for (int j = 0; j < 4; ++j)
                    rout[(size_t)m * Oo + n0 + tx * 4 + j] = acc[i][j];
            }
        }
        gridsync(phase);
    }
}

// ---------------- final stage ----------------
__global__ void offsets_kernel(const float* __restrict__ offW2, const float* __restrict__ offb2,
                               float* __restrict__ out_off, int Np) {
    int warp = (blockIdx.x * blockDim.x + threadIdx.x) >> 5;
    int lane = threadIdx.x & 31;
    if (warp >= Np) return;
    const float* row = g_buf + (size_t)warp * MHh;
    float s = 0.f;
#pragma unroll
    for (int k = lane; k < MHh; k += 32) s += row[k] * offW2[k];
#pragma unroll
    for (int o = 16; o; o >>= 1) s += __shfl_xor_sync(0xFFFFFFFFu, s, o);
    if (lane == 0) out_off[warp] = s + offb2[0];
}

__global__ void gather_out(const int* __restrict__ pack_idx, float* __restrict__ out, int Np) {
    int gid = blockIdx.x * blockDim.x + threadIdx.x;
    if (gid >= Np * Oo) return;
    int i = gid >> 7, o = gid & 127;
    size_t p = (size_t)pack_idx[i];
    float v1 = g_b2cat[o];
#pragma unroll
    for (int s = 0; s < KSC; ++s) v1 += g_rp[s][p * Oo + o];
    size_t NO = (size_t)Np * Oo;
    out[(size_t)i * Oo + o] = v1;                 // flat_p1
    out[2 * NO + Np + (size_t)i * Oo + o] = v1;   // flat_out (== flat_p1)
}

// ---------------- host ----------------
static float* gsymf(const void* symbol) {
    void* p = nullptr;
    cudaGetSymbolAddress(&p, symbol);
    return (float*)p;
}

extern "C" void kernel_launch(void* const* d_in, const int* in_sizes, int n_in,
                              void* d_out, int out_size) {
    const float* features = (const float*)d_in[0];
    const float* W_f2h    = (const float*)d_in[1];
    const float* b_f2h    = (const float*)d_in[2];
    const float* W_ih     = (const float*)d_in[3];
    const float* W_hh     = (const float*)d_in[4];
    const float* b_ih     = (const float*)d_in[5];
    const float* b_hh     = (const float*)d_in[6];
    const float* p1_W1    = (const float*)d_in[7];
    const float* p1_b1    = (const float*)d_in[8];
    const float* p1_W2    = (const float*)d_in[9];
    const float* p1_b2    = (const float*)d_in[10];
    const float* p2_W1    = (const float*)d_in[11];
    const float* p2_b1    = (const float*)d_in[12];
    const float* p2_W2    = (const float*)d_in[13];
    const float* p2_b2    = (const float*)d_in[14];
    const float* off_W1   = (const float*)d_in[15];
    const float* off_b1   = (const float*)d_in[16];
    const float* off_W2   = (const float*)d_in[17];
    const float* off_b2   = (const float*)d_in[18];
    const int*   lengths  = (const int*)d_in[19];
    const int*   pack_idx = (const int*)d_in[20];
    float* out = (float*)d_out;
    const int Np = in_sizes[20];
    const size_t NO = (size_t)Np * Oo;
    const unsigned mT = (unsigned)((Np + 63) / 64);

    float* p_Wf2hT  = gsymf(g_Wf2hT);
    float* p_bhc    = gsymf(g_bhc);
    float* p_W12T   = gsymf(g_W12T);
    float* p_b12    = gsymf(g_b12);
    float* p_W2T2   = gsymf(g_W2T2);
    float* p_b2cat  = gsymf(g_b2cat);
    float* p_offW1T = gsymf(g_offW1T);
    float* p_hs     = gsymf(g_hs);
    float* p_buf    = gsymf(g_buf);

    auto blocks = [](long long n) { return (unsigned)((n + 255) / 256); };

    // launch 1-2: prep ; launch 3: init GEMM ; launch 4: the scan (ncu captures #4)
    k_prepA<<<blocks(4LL * Hh * Hh), TPB>>>(W_ih, W_hh, b_ih, b_hh, W_f2h, b_f2h);
    k_prepB<<<blocks((long long)Hh * 2 * MHh), TPB>>>(p1_W1, p2_W1, p1_b1, p2_b1,
                                                      p1_W2, p2_W2, p1_b2, p2_b2,
                                                      off_W1, lengths);
    gemmG<2><<<dim3(16, 4), TPB>>>(features, Ff, nullptr, p_Wf2hT, 2 * Hh, p_bhc,
                                   nullptr, nullptr, Bsz, 2 * Hh, Ff);
    persistent_scan<<<NB, TPB>>>();

    // post-loop over packed rows
    // offsets hidden = tanh(hs_packed @ offW1T + off_b1) -> g_buf [Np x 512]
    gemmG<1><<<dim3(8, mT), TPB>>>(p_hs, Hh, pack_idx, p_offW1T, MHh, off_b1,
                                   p_buf, nullptr, Np, MHh, Hh);
    offsets_kernel<<<(Np + 7) / 8, TPB>>>(off_W2, off_b2, out + 2 * NO, Np);

    // p2 hidden = tanh(hs_packed @ W12T[:,512:] + b12') -> g_buf (reuse after offsets)
    gemmG<1><<<dim3(8, mT), TPB>>>(p_hs, Hh, pack_idx, p_W12T + MHh, 2 * MHh, p_b12 + MHh,
                                   p_buf, nullptr, Np, MHh, Hh);
    gemmG<0><<<dim3(2, mT), TPB>>>(p_buf, MHh, nullptr, p_W2T2, Oo, p_b2cat + Oo,
                                   out + NO, nullptr, Np, Oo, MHh);

    // gather p1 / flat_out from P3 partials
    gather_out<<<blocks((long long)Np * Oo), TPB>>>(pack_idx, out, Np);
}

// round 9
// speedup vs baseline: 1.8881x; 1.0943x over previous
#include <cuda_runtime.h>
#include <math.h>
#include <stdint.h>

#define Bsz 256
#define Tt  512
#define Hh  512
#define Oo  128
#define MHh 512
#define Ff  256
#define NB  148
#define TPB 256
#define KSC 4      // P3 K-split factor
#define PAP 68     // mac64 A-tile pitch
#define TP  132    // tile128 smem pitch

// ---------------- device scratch ----------------
__device__ float g_WihI [Oo * 4 * Hh];      // [k][j*4+g]
__device__ float g_WhhI [Hh * 4 * Hh];
__device__ float g_bgI  [4 * Hh];
__device__ float g_Wf2hT[Ff * 2 * Hh];
__device__ float g_bhc  [2 * Hh];
__device__ float g_W12T [Hh * 2 * MHh];     // [k][p1|p2]
__device__ float g_b12  [2 * MHh];
__device__ float g_W2T1 [MHh * Oo];
__device__ float g_W2T2 [MHh * Oo];
__device__ float g_b2cat[2 * Oo];
__device__ float g_offW1T[Hh * MHh];

__device__ float g_hb[2][Bsz * Hh];
__device__ float g_cb[2][Bsz * Hh];
__device__ float g_gp[8][Bsz * 4 * Hh];              // P0 partials (ks_a<=8)
__device__ float g_qp[8][Bsz * MHh];                 // P2 partials (ks_b=8)
__device__ float g_rp[KSC][(size_t)Tt * Bsz * Oo];   // P3 partials per t
__device__ float g_hs [(size_t)Tt * Bsz * Hh];
__device__ float g_buf[(size_t)Tt * Bsz * MHh];
__device__ int   g_nt[Tt];
__device__ unsigned g_barCount;

// ---------------- preprocessing (2 launches) ----------------
__global__ void k_prepA(const float* __restrict__ W_ih, const float* __restrict__ W_hh,
                        const float* __restrict__ b_ih, const float* __restrict__ b_hh,
                        const float* __restrict__ W_f2h, const float* __restrict__ b_f2h) {
    int i = blockIdx.x * blockDim.x + threadIdx.x;
    if (i < Hh * 4 * Hh) {
        int k = i / 2048, n = i % 2048, j = n >> 2, g = n & 3;
        g_WhhI[i] = W_hh[(size_t)(g * Hh + j) * Hh + k];
    }
    if (i < Oo * 4 * Hh) {
        int k = i / 2048, n = i % 2048, j = n >> 2, g = n & 3;
        g_WihI[i] = W_ih[(size_t)(g * Hh + j) * Oo + k];
    }
    if (i < 4 * Hh) {
        int j = i >> 2, g = i & 3;
        g_bgI[i] = b_ih[g * Hh + j] + b_hh[g * Hh + j];
    }
    if (i < Ff * 2 * Hh) {
        int k = i / (2 * Hh), j = i % (2 * Hh);
        int src = (j < Hh) ? 2 * j : 2 * (j - Hh) + 1;
        g_Wf2hT[i] = W_f2h[(size_t)src * Ff + k];
    }
    if (i < 2 * Hh) {
        int src = (i < Hh) ? 2 * i : 2 * (i - Hh) + 1;
        g_bhc[i] = b_f2h[src];
    }
}

__global__ void k_prepB(const float* __restrict__ p1_W1, const float* __restrict__ p2_W1,
                        const float* __restrict__ p1_b1, const float* __restrict__ p2_b1,
                        const float* __restrict__ p1_W2, const float* __restrict__ p2_W2,
                        const float* __restrict__ p1_b2, const float* __restrict__ p2_b2,
                        const float* __restrict__ off_W1, const int* __restrict__ lengths) {
    int i = blockIdx.x * blockDim.x + threadIdx.x;
    if (i < Hh * 2 * MHh) {
        int k = i / (2 * MHh), n = i % (2 * MHh);
        g_W12T[i] = (n < MHh) ? p1_W1[(size_t)n * Hh + k]
                              : p2_W1[(size_t)(n - MHh) * Hh + k];
    }
    if (i < MHh * Oo) {
        int k = i >> 7, n = i & 127;
        g_W2T1[i] = p1_W2[(size_t)n * MHh + k];
        g_W2T2[i] = p2_W2[(size_t)n * MHh + k];
    }
    if (i < MHh * Hh) {
        int r = i / Hh, c = i % Hh;
        g_offW1T[(size_t)c * MHh + r] = off_W1[i];
    }
    if (i < 2 * MHh) g_b12[i] = (i < MHh) ? p1_b1[i] : p2_b1[i - MHh];
    if (i < 2 * Oo)  g_b2cat[i] = (i < Oo) ? p1_b2[i] : p2_b2[i - Oo];
    if (i == 0) g_barCount = 0u;
    if (i < Tt) {
        int c = 0;
        for (int b = 0; b < Bsz; ++b) c += (lengths[b] > i) ? 1 : 0;
        g_nt[i] = c;
    }
}

// ---------------- 128x128 tile engine (8x8 micro, scalar FFMA) ----------------
// AF4(m_local, k_local) -> float4 of 4 consecutive k; BF4(k_local, n_local) -> float4 of n.
template <class AF4, class BF4>
__device__ __forceinline__ void tile128(float (&acc)[2][2][4][4], int K, AF4 af4, BF4 bf4,
                                        float* As, float* Bs) {
    const int tid = threadIdx.x;
    const int tx = tid & 15, ty = tid >> 4;
    const int la_k = (tid & 3) * 4;   // A: k offset (0,4,8,12)
    const int la_m = tid >> 2;        // A: m in 0..63 (also +64)
    const int lb_n = (tid & 31) * 4;  // B: n offset
    const int lb_r = tid >> 5;        // B: k row 0..7 (also +8)

    float4 pa0 = af4(la_m, la_k);
    float4 pa1 = af4(la_m + 64, la_k);
    float4 pb0 = bf4(lb_r, lb_n);
    float4 pb1 = bf4(lb_r + 8, lb_n);

    for (int kt = 0; kt < K; kt += 16) {
        // A transpose store (scalar)
        float* a0p = &As[la_k * TP + la_m];
        a0p[0] = pa0.x; a0p[TP] = pa0.y; a0p[2 * TP] = pa0.z; a0p[3 * TP] = pa0.w;
        float* a1p = a0p + 64;
        a1p[0] = pa1.x; a1p[TP] = pa1.y; a1p[2 * TP] = pa1.z; a1p[3 * TP] = pa1.w;
        *(float4*)&Bs[lb_r * TP + lb_n] = pb0;
        *(float4*)&Bs[(lb_r + 8) * TP + lb_n] = pb1;
        __syncthreads();
        if (kt + 16 < K) {
            const int k1 = kt + 16;
            pa0 = af4(la_m, k1 + la_k);
            pa1 = af4(la_m + 64, k1 + la_k);
            pb0 = bf4(k1 + lb_r, lb_n);
            pb1 = bf4(k1 + lb_r + 8, lb_n);
        }
#pragma unroll
        for (int k = 0; k < 16; ++k) {
            float4 a0 = *(const float4*)&As[k * TP + ty * 4];
            float4 a1 = *(const float4*)&As[k * TP + 64 + ty * 4];
            float4 b0 = *(const float4*)&Bs[k * TP + tx * 4];
            float4 b1 = *(const float4*)&Bs[k * TP + 64 + tx * 4];
            float av[2][4] = {{a0.x, a0.y, a0.z, a0.w}, {a1.x, a1.y, a1.z, a1.w}};
            float bv[2][4] = {{b0.x, b0.y, b0.z, b0.w}, {b1.x, b1.y, b1.z, b1.w}};
#pragma unroll
            for (int ih = 0; ih < 2; ++ih)
#pragma unroll
                for (int jh = 0; jh < 2; ++jh)
#pragma unroll
                    for (int i = 0; i < 4; ++i)
#pragma unroll
                        for (int j = 0; j < 4; ++j)
                            acc[ih][jh][i][j] += av[ih][i] * bv[jh][j];
        }
        __syncthreads();
    }
}

// ---------------- 64x64 MAC core (P2/P3, short K) ----------------
template <class AF, class BF>
__device__ __forceinline__ void mac64(float (&acc)[4][4], int K, AF af, BF bf,
                                      float* As, float* Bs) {
    const int tid = threadIdx.x;
    const int tx = tid & 15, ty = tid >> 4;
    const int bk = tid >> 6, bn = tid & 63;
    float ra[4], rb[4];
#pragma unroll
    for (int i = 0; i < 4; ++i) ra[i] = af(ty * 4 + i, tx);
#pragma unroll
    for (int i = 0; i < 4; ++i) rb[i] = bf(bk + i * 4, bn);

    for (int kt = 0; kt < K; kt += 16) {
        *(float4*)&As[tx * PAP + ty * 4] = make_float4(ra[0], ra[1], ra[2], ra[3]);
#pragma unroll
        for (int i = 0; i < 4; ++i) Bs[(bk + i * 4) * 64 + bn] = rb[i];
        __syncthreads();
        if (kt + 16 < K) {
#pragma unroll
            for (int i = 0; i < 4; ++i) ra[i] = af(ty * 4 + i, kt + 16 + tx);
#pragma unroll
            for (int i = 0; i < 4; ++i) rb[i] = bf(kt + 16 + bk + i * 4, bn);
        }
#pragma unroll
        for (int k = 0; k < 16; ++k) {
            float4 a4 = *(const float4*)&As[k * PAP + ty * 4];
            float4 b4 = *(const float4*)&Bs[k * 64 + tx * 4];
            float av[4] = {a4.x, a4.y, a4.z, a4.w};
            float bv[4] = {b4.x, b4.y, b4.z, b4.w};
#pragma unroll
            for (int i = 0; i < 4; ++i)
#pragma unroll
                for (int j = 0; j < 4; ++j) acc[i][j] += av[i] * bv[j];
        }
        __syncthreads();
    }
}

// ---------------- generic GEMM on tile128 ----------------
// MODE 0: C=acc+bias ; 1: tanh ; 2: h/c split init
template <int MODE>
__global__ void __launch_bounds__(256)
gemmG(const float* __restrict__ A, int lda, const int* __restrict__ aidx,
      const float* __restrict__ Bm, int ldb, const float* __restrict__ bias,
      float* __restrict__ C, int M, int N, int K) {
    __shared__ __align__(16) float As[16 * TP];
    __shared__ __align__(16) float Bs[16 * TP];
    const int n0 = blockIdx.x * 128;
    const int m0 = blockIdx.y * 128;
    const int tx = threadIdx.x & 15, ty = threadIdx.x >> 4;

    float acc[2][2][4][4] = {};

    auto af4 = [&](int ml, int kk) -> float4 {
        int m = m0 + ml;
        if (m >= M) return make_float4(0.f, 0.f, 0.f, 0.f);
        int row = aidx ? aidx[m] : m;
        return *(const float4*)&A[(size_t)row * lda + kk];
    };
    auto bf4 = [&](int kk, int nl) -> float4 {
        return *(const float4*)&Bm[(size_t)kk * ldb + n0 + nl];
    };
    tile128(acc, K, af4, bf4, As, Bs);

#pragma unroll
    for (int ih = 0; ih < 2; ++ih)
#pragma unroll
        for (int i = 0; i < 4; ++i) {
            int m = m0 + ih * 64 + ty * 4 + i;
            if (m >= M) continue;
#pragma unroll
            for (int jh = 0; jh < 2; ++jh)
#pragma unroll
                for (int j = 0; j < 4; ++j) {
                    int n = n0 + jh * 64 + tx * 4 + j;
                    float r = acc[ih][jh][i][j] + (bias ? bias[n] : 0.f);
                    if (MODE == 1) r = tanhf(r);
                    if (MODE == 2) {
                        if (n < Hh) g_hb[0][m * Hh + n] = r;
                        else        g_cb[0][m * Hh + (n - Hh)] = r;
                    } else {
                        C[(size_t)m * N + n] = r;
                    }
                }
        }
}

// ---------------- persistent scan ----------------
__device__ __forceinline__ float sigm(float x) { return 1.f / (1.f + expf(-x)); }

__device__ __forceinline__ void gridsync(unsigned& phase) {
    __syncthreads();
    if (threadIdx.x == 0) {
        __threadfence();
        phase += 1u;
        const unsigned target = phase * NB;
        atomicAdd(&g_barCount, 1u);
        while (*((volatile unsigned*)&g_barCount) < target) { __nanosleep(64); }
        __threadfence();
    }
    __syncthreads();
}

__global__ void __launch_bounds__(TPB, 1) persistent_scan() {
    __shared__ __align__(16) float As[16 * TP];
    __shared__ __align__(16) float Bs[16 * TP];
    const int bid = blockIdx.x;
    const int tid = threadIdx.x;
    const int tx = tid & 15, ty = tid >> 4;
    unsigned phase = 0;

    for (int t = 0; t < Tt; ++t) {
        const int nt = g_nt[t];
        const int mt   = (nt + 63) >> 6;    // 64-row tiles (P1/P2/P3)
        const int m128 = (nt + 127) >> 7;   // 128-row tiles (P0)
        const int rd = t & 1, wr = rd ^ 1;
        const float* __restrict__ hR = g_hb[rd];
        float* __restrict__ hW = g_hb[wr];
        const float* __restrict__ cR = g_cb[rd];
        float* __restrict__ cW = g_cb[wr];
        const bool hasx = (t > 0);
        const int xoff = hasx ? 128 : 0;
        const int kspace = Hh + xoff;                  // 640 or 512
        const int ks_a = (m128 == 2) ? 4 : 8;
        const int Ka = kspace / ks_a;                  // 160/80 or 128/64
        const size_t rbase = hasx ? (size_t)(t - 1) * Bsz * Oo : 0;

        // ---- P0: gates partials = x@WihI + h@WhhI (tile128, K-split) ----
        const int tilesA = m128 * 16 * ks_a;
        for (int tile = bid; tile < tilesA; tile += NB) {
            const int s  = tile % ks_a;
            const int u  = tile / ks_a;
            const int n0 = (u & 15) << 7;
            const int m0 = (u >> 4) << 7;
            const int k0 = s * Ka;

            float acc[2][2][4][4] = {};
            auto af4 = [&](int ml, int kk) -> float4 {
                int gk = k0 + kk;
                int m = m0 + ml;
                if (hasx && gk < Oo) {
                    size_t ix = rbase + (size_t)m * Oo + gk;
                    float4 v = *(const float4*)&g_b2cat[gk];
#pragma unroll
                    for (int sc = 0; sc < KSC; ++sc) {
                        float4 r = *(const float4*)&g_rp[sc][ix];
                        v.x += r.x; v.y += r.y; v.z += r.z; v.w += r.w;
                    }
                    return v;
                }
                return *(const float4*)&hR[m * Hh + gk - xoff];
            };
            auto bf4 = [&](int kk, int nl) -> float4 {
                int gk = k0 + kk;
                const float* src = (hasx && gk < Oo)
                    ? &g_WihI[gk * 2048 + n0 + nl]
                    : &g_WhhI[(size_t)(gk - xoff) * 2048 + n0 + nl];
                return *(const float4*)src;
            };
            tile128(acc, Ka, af4, bf4, As, Bs);

            float* __restrict__ gout = g_gp[s];
#pragma unroll
            for (int ih = 0; ih < 2; ++ih)
#pragma unroll
                for (int i = 0; i < 4; ++i) {
                    int m = m0 + ih * 64 + ty * 4 + i;
                    float* dst = &gout[m * 2048 + n0];
#pragma unroll
                    for (int jh = 0; jh < 2; ++jh)
                        *(float4*)&dst[jh * 64 + tx * 4] =
                            make_float4(acc[ih][jh][i][0], acc[ih][jh][i][1],
                                        acc[ih][jh][i][2], acc[ih][jh][i][3]);
                }
        }
        gridsync(phase);

        // ---- P1: LSTM combine (sum ks_a partials + bias) ----
        {
            const int total = mt * 64 * Hh;
            for (int e = bid * TPB + tid; e < total; e += NB * TPB) {
                int m = e >> 9, j = e & (Hh - 1);
                if (m < nt) {
                    float4 gs = make_float4(0.f, 0.f, 0.f, 0.f);
                    for (int s = 0; s < ks_a; ++s) {
                        float4 gp = *(const float4*)&g_gp[s][m * 2048 + j * 4];
                        gs.x += gp.x; gs.y += gp.y; gs.z += gp.z; gs.w += gp.w;
                    }
                    float4 bg = *(const float4*)&g_bgI[j * 4];
                    float cn = sigm(gs.y + bg.y) * cR[m * Hh + j] +
                               sigm(gs.x + bg.x) * tanhf(gs.z + bg.z);
                    float hn = sigm(gs.w + bg.w) * tanhf(cn);
                    cW[m * Hh + j] = cn;
                    hW[m * Hh + j] = hn;
                    g_hs[((size_t)t * Bsz + m) * Hh + j] = hn;
                }
            }
            gridsync(phase);
        }

        // ---- P2: q partials = h_t @ W12T[:, 0:512], K-split 8 (mac64) ----
        const int Kb = MHh / 8;   // 64
        const int tilesB = mt * 8 * 8;
        for (int tile = bid; tile < tilesB; tile += NB) {
            const int s  = tile & 7;
            const int u  = tile >> 3;
            const int n0 = (u & 7) << 6;
            const int m0 = (u >> 3) << 6;
            const int k0 = s * Kb;
            float* __restrict__ qout = g_qp[s];
            float acc[4][4] = {};
            auto af = [&](int ml, int kk) -> float { return hW[(m0 + ml) * Hh + k0 + kk]; };
            auto bf = [&](int kk, int nl) -> float {
                return g_W12T[(size_t)(k0 + kk) * 1024 + n0 + nl];
            };
            mac64(acc, Kb, af, bf, As, Bs);
#pragma unroll
            for (int i = 0; i < 4; ++i) {
                int m = m0 + ty * 4 + i;
#pragma unroll
                for (int j = 0; j < 4; ++j)
                    qout[m * MHh + n0 + tx * 4 + j] = acc[i][j];
            }
        }
        gridsync(phase);

        // ---- P3: p1 partials = tanh(sum q + b12) @ W2T1, K-split 4 (mac64) ----
        const int Kc = MHh / KSC;    // 128
        const int tilesC = mt * 2 * KSC;
        for (int tile = bid; tile < tilesC; tile += NB) {
            const int s  = tile % KSC;
            const int u  = tile / KSC;
            const int n0 = (u & 1) << 6;
            const int m0 = (u >> 1) << 6;
            const int k0 = s * Kc;
            float* __restrict__ rout = g_rp[s] + (size_t)t * Bsz * Oo;
            float acc[4][4] = {};
            auto af = [&](int ml, int kk) -> float {
                int k = k0 + kk;
                float v = g_b12[k];
#pragma unroll
                for (int s2 = 0; s2 < 8; ++s2) v += g_qp[s2][(m0 + ml) * MHh + k];
                return tanhf(v);
            };
            auto bf = [&](int kk, int nl) -> float { return g_W2T1[(k0 + kk) * Oo + n0 + nl]; };
            mac64(acc, Kc, af, bf, As, Bs);
#pragma unroll
            for (int i = 0; i < 4; ++i) {
                int m = m0 + ty * 4 + i;
#pragma unroll
                for (int j = 0; j < 4; ++j)
                    rout[(size_t)m * Oo + n0 + tx * 4 + j] = acc[i][j];
            }
        }
        gridsync(phase);
    }
}

// ---------------- final stage ----------------
__global__ void offsets_kernel(const float* __restrict__ offW2, const float* __restrict__ offb2,
                               float* __restrict__ out_off, int Np) {
    int warp = (blockIdx.x * blockDim.x + threadIdx.x) >> 5;
    int lane = threadIdx.x & 31;
    if (warp >= Np) return;
    const float* row = g_buf + (size_t)warp * MHh;
    float s = 0.f;
#pragma unroll
    for (int k = lane; k < MHh; k += 32) s += row[k] * offW2[k];
#pragma unroll
    for (int o = 16; o; o >>= 1) s += __shfl_xor_sync(0xFFFFFFFFu, s, o);
    if (lane == 0) out_off[warp] = s + offb2[0];
}

__global__ void gather_out(const int* __restrict__ pack_idx, float* __restrict__ out, int Np) {
    int gid = blockIdx.x * blockDim.x + threadIdx.x;
    if (gid >= Np * Oo) return;
    int i = gid >> 7, o = gid & 127;
    size_t p = (size_t)pack_idx[i];
    float v1 = g_b2cat[o];
#pragma unroll
    for (int s = 0; s < KSC; ++s) v1 += g_rp[s][p * Oo + o];
    size_t NO = (size_t)Np * Oo;
    out[(size_t)i * Oo + o] = v1;                 // flat_p1
    out[2 * NO + Np + (size_t)i * Oo + o] = v1;   // flat_out (== flat_p1)
}

// ---------------- host ----------------
static float* gsymf(const void* symbol) {
    void* p = nullptr;
    cudaGetSymbolAddress(&p, symbol);
    return (float*)p;
}

extern "C" void kernel_launch(void* const* d_in, const int* in_sizes, int n_in,
                              void* d_out, int out_size) {
    const float* features = (const float*)d_in[0];
    const float* W_f2h    = (const float*)d_in[1];
    const float* b_f2h    = (const float*)d_in[2];
    const float* W_ih     = (const float*)d_in[3];
    const float* W_hh     = (const float*)d_in[4];
    const float* b_ih     = (const float*)d_in[5];
    const float* b_hh     = (const float*)d_in[6];
    const float* p1_W1    = (const float*)d_in[7];
    const float* p1_b1    = (const float*)d_in[8];
    const float* p1_W2    = (const float*)d_in[9];
    const float* p1_b2    = (const float*)d_in[10];
    const float* p2_W1    = (const float*)d_in[11];
    const float* p2_b1    = (const float*)d_in[12];
    const float* p2_W2    = (const float*)d_in[13];
    const float* p2_b2    = (const float*)d_in[14];
    const float* off_W1   = (const float*)d_in[15];
    const float* off_b1   = (const float*)d_in[16];
    const float* off_W2   = (const float*)d_in[17];
    const float* off_b2   = (const float*)d_in[18];
    const int*   lengths  = (const int*)d_in[19];
    const int*   pack_idx = (const int*)d_in[20];
    float* out = (float*)d_out;
    const int Np = in_sizes[20];
    const size_t NO = (size_t)Np * Oo;
    const unsigned mT = (unsigned)((Np + 127) / 128);

    float* p_Wf2hT  = gsymf(g_Wf2hT);
    float* p_bhc    = gsymf(g_bhc);
    float* p_W12T   = gsymf(g_W12T);
    float* p_b12    = gsymf(g_b12);
    float* p_W2T2   = gsymf(g_W2T2);
    float* p_b2cat  = gsymf(g_b2cat);
    float* p_offW1T = gsymf(g_offW1T);
    float* p_hs     = gsymf(g_hs);
    float* p_buf    = gsymf(g_buf);

    auto blocks = [](long long n) { return (unsigned)((n + 255) / 256); };

    // launch 1-2: prep ; launch 3: init GEMM ; launch 4: the scan (ncu captures #4)
    k_prepA<<<blocks(4LL * Hh * Hh), TPB>>>(W_ih, W_hh, b_ih, b_hh, W_f2h, b_f2h);
    k_prepB<<<blocks((long long)Hh * 2 * MHh), TPB>>>(p1_W1, p2_W1, p1_b1, p2_b1,
                                                      p1_W2, p2_W2, p1_b2, p2_b2,
                                                      off_W1, lengths);
    gemmG<2><<<dim3(8, 2), TPB>>>(features, Ff, nullptr, p_Wf2hT, 2 * Hh, p_bhc,
                                  nullptr, Bsz, 2 * Hh, Ff);
    persistent_scan<<<NB, TPB>>>();

    // post-loop over packed rows
    // offsets hidden = tanh(hs_packed @ offW1T + off_b1) -> g_buf [Np x 512]
    gemmG<1><<<dim3(4, mT), TPB>>>(p_hs, Hh, pack_idx, p_offW1T, MHh, off_b1,
                                   p_buf, Np, MHh, Hh);
    offsets_kernel<<<(Np + 7) / 8, TPB>>>(off_W2, off_b2, out + 2 * NO, Np);

    // p2 hidden = tanh(hs_packed @ W12T[:,512:] + b12') -> g_buf (reuse after offsets)
    gemmG<1><<<dim3(4, mT), TPB>>>(p_hs, Hh, pack_idx, p_W12T + MHh, 2 * MHh, p_b12 + MHh,
                                   p_buf, Np, MHh, Hh);
    gemmG<0><<<dim3(1, mT), TPB>>>(p_buf, MHh, nullptr, p_W2T2, Oo, p_b2cat + Oo,
                                   out + NO, Np, Oo, MHh);

    // gather p1 / flat_out from P3 partials
    gather_out<<<blocks((long long)Np * Oo), TPB>>>(pack_idx, out, Np);
}

// round 10
// speedup vs baseline: 1.9375x; 1.0261x over previous
#include <cuda_runtime.h>
#include <math.h>
#include <stdint.h>

#define Bsz 256
#define Tt  512
#define Hh  512
#define Oo  128
#define MHh 512
#define Ff  256
#define NB  148
#define TPB 256
#define KSC 4      // P3 K-split factor
#define PAP 68     // mac64 A-tile pitch
#define TP  132    // tile128 smem pitch

// ---------------- device scratch ----------------
__device__ float g_WihI [Oo * 4 * Hh];      // [k][j*4+g]
__device__ float g_WhhI [Hh * 4 * Hh];
__device__ float g_bgI  [4 * Hh];
__device__ float g_Wf2hT[Ff * 2 * Hh];
__device__ float g_bhc  [2 * Hh];
__device__ float g_W12T [Hh * 2 * MHh];     // [k][p1|p2]
__device__ float g_b12  [2 * MHh];
__device__ float g_W2T1 [MHh * Oo];
__device__ float g_W2T2 [MHh * Oo];
__device__ float g_b2cat[2 * Oo];
__device__ float g_offW1T[Hh * MHh];

__device__ float g_hb[2][Bsz * Hh];
__device__ float g_cb[2][Bsz * Hh];
__device__ float g_gp[8][Bsz * 4 * Hh];              // P0 partials (ks_a<=8)
__device__ float g_qp[8][Bsz * MHh];                 // P2 partials (ks_b=8)
__device__ float g_rp[KSC][(size_t)Tt * Bsz * Oo];   // P3 partials per t
__device__ float g_hs [(size_t)Tt * Bsz * Hh];
__device__ float g_buf[(size_t)Tt * Bsz * MHh];
__device__ int   g_nt[Tt];
__device__ unsigned g_barCount;

// ---------------- fast-safe activations (err ~1e-6, threshold is 1e-3) ------
__device__ __forceinline__ float sigm(float x) {
    return __fdividef(1.f, 1.f + __expf(-x));
}
__device__ __forceinline__ float tanh_f(float x) {
    return 1.f - __fdividef(2.f, __expf(2.f * x) + 1.f);
}

// ---------------- preprocessing (2 launches) ----------------
__global__ void k_prepA(const float* __restrict__ W_ih, const float* __restrict__ W_hh,
                        const float* __restrict__ b_ih, const float* __restrict__ b_hh,
                        const float* __restrict__ W_f2h, const float* __restrict__ b_f2h) {
    int i = blockIdx.x * blockDim.x + threadIdx.x;
    if (i < Hh * 4 * Hh) {
        int k = i / 2048, n = i % 2048, j = n >> 2, g = n & 3;
        g_WhhI[i] = W_hh[(size_t)(g * Hh + j) * Hh + k];
    }
    if (i < Oo * 4 * Hh) {
        int k = i / 2048, n = i % 2048, j = n >> 2, g = n & 3;
        g_WihI[i] = W_ih[(size_t)(g * Hh + j) * Oo + k];
    }
    if (i < 4 * Hh) {
        int j = i >> 2, g = i & 3;
        g_bgI[i] = b_ih[g * Hh + j] + b_hh[g * Hh + j];
    }
    if (i < Ff * 2 * Hh) {
        int k = i / (2 * Hh), j = i % (2 * Hh);
        int src = (j < Hh) ? 2 * j : 2 * (j - Hh) + 1;
        g_Wf2hT[i] = W_f2h[(size_t)src * Ff + k];
    }
    if (i < 2 * Hh) {
        int src = (i < Hh) ? 2 * i : 2 * (i - Hh) + 1;
        g_bhc[i] = b_f2h[src];
    }
}

__global__ void k_prepB(const float* __restrict__ p1_W1, const float* __restrict__ p2_W1,
                        const float* __restrict__ p1_b1, const float* __restrict__ p2_b1,
                        const float* __restrict__ p1_W2, const float* __restrict__ p2_W2,
                        const float* __restrict__ p1_b2, const float* __restrict__ p2_b2,
                        const float* __restrict__ off_W1, const int* __restrict__ lengths) {
    int i = blockIdx.x * blockDim.x + threadIdx.x;
    if (i < Hh * 2 * MHh) {
        int k = i / (2 * MHh), n = i % (2 * MHh);
        g_W12T[i] = (n < MHh) ? p1_W1[(size_t)n * Hh + k]
                              : p2_W1[(size_t)(n - MHh) * Hh + k];
    }
    if (i < MHh * Oo) {
        int k = i >> 7, n = i & 127;
        g_W2T1[i] = p1_W2[(size_t)n * MHh + k];
        g_W2T2[i] = p2_W2[(size_t)n * MHh + k];
    }
    if (i < MHh * Hh) {
        int r = i / Hh, c = i % Hh;
        g_offW1T[(size_t)c * MHh + r] = off_W1[i];
    }
    if (i < 2 * MHh) g_b12[i] = (i < MHh) ? p1_b1[i] : p2_b1[i - MHh];
    if (i < 2 * Oo)  g_b2cat[i] = (i < Oo) ? p1_b2[i] : p2_b2[i - Oo];
    if (i == 0) g_barCount = 0u;
    if (i < Tt) {
        int c = 0;
        for (int b = 0; b < Bsz; ++b) c += (lengths[b] > i) ? 1 : 0;
        g_nt[i] = c;
    }
}

// ---------------- 128x128 tile engine (8x8 micro, scalar FFMA) ----------------
template <class AF4, class BF4>
__device__ __forceinline__ void tile128(float (&acc)[2][2][4][4], int K, AF4 af4, BF4 bf4,
                                        float* As, float* Bs) {
    const int tid = threadIdx.x;
    const int tx = tid & 15, ty = tid >> 4;
    const int la_k = (tid & 3) * 4;
    const int la_m = tid >> 2;
    const int lb_n = (tid & 31) * 4;
    const int lb_r = tid >> 5;

    float4 pa0 = af4(la_m, la_k);
    float4 pa1 = af4(la_m + 64, la_k);
    float4 pb0 = bf4(lb_r, lb_n);
    float4 pb1 = bf4(lb_r + 8, lb_n);

    for (int kt = 0; kt < K; kt += 16) {
        float* a0p = &As[la_k * TP + la_m];
        a0p[0] = pa0.x; a0p[TP] = pa0.y; a0p[2 * TP] = pa0.z; a0p[3 * TP] = pa0.w;
        float* a1p = a0p + 64;
        a1p[0] = pa1.x; a1p[TP] = pa1.y; a1p[2 * TP] = pa1.z; a1p[3 * TP] = pa1.w;
        *(float4*)&Bs[lb_r * TP + lb_n] = pb0;
        *(float4*)&Bs[(lb_r + 8) * TP + lb_n] = pb1;
        __syncthreads();
        if (kt + 16 < K) {
            const int k1 = kt + 16;
            pa0 = af4(la_m, k1 + la_k);
            pa1 = af4(la_m + 64, k1 + la_k);
            pb0 = bf4(k1 + lb_r, lb_n);
            pb1 = bf4(k1 + lb_r + 8, lb_n);
        }
#pragma unroll
        for (int k = 0; k < 16; ++k) {
            float4 a0 = *(const float4*)&As[k * TP + ty * 4];
            float4 a1 = *(const float4*)&As[k * TP + 64 + ty * 4];
            float4 b0 = *(const float4*)&Bs[k * TP + tx * 4];
            float4 b1 = *(const float4*)&Bs[k * TP + 64 + tx * 4];
            float av[2][4] = {{a0.x, a0.y, a0.z, a0.w}, {a1.x, a1.y, a1.z, a1.w}};
            float bv[2][4] = {{b0.x, b0.y, b0.z, b0.w}, {b1.x, b1.y, b1.z, b1.w}};
#pragma unroll
            for (int ih = 0; ih < 2; ++ih)
#pragma unroll
                for (int jh = 0; jh < 2; ++jh)
#pragma unroll
                    for (int i = 0; i < 4; ++i)
#pragma unroll
                        for (int j = 0; j < 4; ++j)
                            acc[ih][jh][i][j] += av[ih][i] * bv[jh][j];
        }
        __syncthreads();
    }
}

// ---------------- 64x64 MAC core ----------------
template <class AF, class BF>
__device__ __forceinline__ void mac64(float (&acc)[4][4], int K, AF af, BF bf,
                                      float* As, float* Bs) {
    const int tid = threadIdx.x;
    const int tx = tid & 15, ty = tid >> 4;
    const int bk = tid >> 6, bn = tid & 63;
    float ra[4], rb[4];
#pragma unroll
    for (int i = 0; i < 4; ++i) ra[i] = af(ty * 4 + i, tx);
#pragma unroll
    for (int i = 0; i < 4; ++i) rb[i] = bf(bk + i * 4, bn);

    for (int kt = 0; kt < K; kt += 16) {
        *(float4*)&As[tx * PAP + ty * 4] = make_float4(ra[0], ra[1], ra[2], ra[3]);
#pragma unroll
        for (int i = 0; i < 4; ++i) Bs[(bk + i * 4) * 64 + bn] = rb[i];
        __syncthreads();
        if (kt + 16 < K) {
#pragma unroll
            for (int i = 0; i < 4; ++i) ra[i] = af(ty * 4 + i, kt + 16 + tx);
#pragma unroll
            for (int i = 0; i < 4; ++i) rb[i] = bf(kt + 16 + bk + i * 4, bn);
        }
#pragma unroll
        for (int k = 0; k < 16; ++k) {
            float4 a4 = *(const float4*)&As[k * PAP + ty * 4];
            float4 b4 = *(const float4*)&Bs[k * 64 + tx * 4];
            float av[4] = {a4.x, a4.y, a4.z, a4.w};
            float bv[4] = {b4.x, b4.y, b4.z, b4.w};
#pragma unroll
            for (int i = 0; i < 4; ++i)
#pragma unroll
                for (int j = 0; j < 4; ++j) acc[i][j] += av[i] * bv[j];
        }
        __syncthreads();
    }
}

// ---------------- generic GEMM on tile128 ----------------
// MODE 0: C=acc+bias ; 1: tanh ; 2: h/c split init
template <int MODE>
__global__ void __launch_bounds__(256)
gemmG(const float* __restrict__ A, int lda, const int* __restrict__ aidx,
      const float* __restrict__ Bm, int ldb, const float* __restrict__ bias,
      float* __restrict__ C, int M, int N, int K) {
    __shared__ __align__(16) float As[16 * TP];
    __shared__ __align__(16) float Bs[16 * TP];
    const int n0 = blockIdx.x * 128;
    const int m0 = blockIdx.y * 128;
    const int tx = threadIdx.x & 15, ty = threadIdx.x >> 4;

    float acc[2][2][4][4] = {};

    auto af4 = [&](int ml, int kk) -> float4 {
        int m = m0 + ml;
        if (m >= M) return make_float4(0.f, 0.f, 0.f, 0.f);
        int row = aidx ? aidx[m] : m;
        return *(const float4*)&A[(size_t)row * lda + kk];
    };
    auto bf4 = [&](int kk, int nl) -> float4 {
        return *(const float4*)&Bm[(size_t)kk * ldb + n0 + nl];
    };
    tile128(acc, K, af4, bf4, As, Bs);

#pragma unroll
    for (int ih = 0; ih < 2; ++ih)
#pragma unroll
        for (int i = 0; i < 4; ++i) {
            int m = m0 + ih * 64 + ty * 4 + i;
            if (m >= M) continue;
#pragma unroll
            for (int jh = 0; jh < 2; ++jh)
#pragma unroll
                for (int j = 0; j < 4; ++j) {
                    int n = n0 + jh * 64 + tx * 4 + j;
                    float r = acc[ih][jh][i][j] + (bias ? bias[n] : 0.f);
                    if (MODE == 1) r = tanh_f(r);
                    if (MODE == 2) {
                        if (n < Hh) g_hb[0][m * Hh + n] = r;
                        else        g_cb[0][m * Hh + (n - Hh)] = r;
                    } else {
                        C[(size_t)m * N + n] = r;
                    }
                }
        }
}

// ---------------- persistent scan ----------------
__device__ __forceinline__ void gridsync(unsigned& phase) {
    __syncthreads();
    if (threadIdx.x == 0) {
        __threadfence();
        phase += 1u;
        const unsigned target = phase * NB;
        atomicAdd(&g_barCount, 1u);
        while (*((volatile unsigned*)&g_barCount) < target) {}
        __threadfence();
    }
    __syncthreads();
}

__global__ void __launch_bounds__(TPB, 1) persistent_scan() {
    __shared__ __align__(16) float As[16 * TP];
    __shared__ __align__(16) float Bs[16 * TP];
    const int bid = blockIdx.x;
    const int tid = threadIdx.x;
    const int tx = tid & 15, ty = tid >> 4;
    unsigned phase = 0;

    for (int t = 0; t < Tt; ++t) {
        const int nt = g_nt[t];
        const int mt   = (nt + 63) >> 6;
        const int m128 = (nt + 127) >> 7;
        const int rd = t & 1, wr = rd ^ 1;
        const float* __restrict__ hR = g_hb[rd];
        float* __restrict__ hW = g_hb[wr];
        const float* __restrict__ cR = g_cb[rd];
        float* __restrict__ cW = g_cb[wr];
        const bool hasx = (t > 0);
        const int xoff = hasx ? 128 : 0;
        const int kspace = Hh + xoff;                  // 640 or 512
        const bool small = (nt <= 64);                 // 64-row P0 path
        const int ks_a = small ? 4 : ((m128 == 2) ? 4 : 8);
        const int Ka = kspace / ks_a;
        const size_t rbase = hasx ? (size_t)(t - 1) * Bsz * Oo : 0;

        // A-operand scalar loader (shared by both P0 paths)
        auto afs = [&](int m, int gk) -> float {
            if (hasx && gk < Oo) {
                size_t ix = rbase + (size_t)m * Oo + gk;
                float v = g_b2cat[gk];
#pragma unroll
                for (int sc = 0; sc < KSC; ++sc) v += g_rp[sc][ix];
                return v;
            }
            return hR[m * Hh + gk - xoff];
        };

        // ---- P0: gates partials = x@WihI + h@WhhI ----
        if (small) {
            // 64x64 tiles: 32 n-tiles x ks_a
            const int tilesA = 32 * ks_a;
            for (int tile = bid; tile < tilesA; tile += NB) {
                const int s  = tile % ks_a;
                const int n0 = (tile / ks_a) << 6;
                const int k0 = s * Ka;
                float acc[4][4] = {};
                auto af = [&](int ml, int kk) -> float { return afs(ml, k0 + kk); };
                auto bf = [&](int kk, int nl) -> float {
                    int gk = k0 + kk;
                    return (hasx && gk < Oo) ? g_WihI[gk * 2048 + n0 + nl]
                                             : g_WhhI[(size_t)(gk - xoff) * 2048 + n0 + nl];
                };
                mac64(acc, Ka, af, bf, As, Bs);
                float* __restrict__ gout = g_gp[s];
#pragma unroll
                for (int i = 0; i < 4; ++i) {
                    int m = ty * 4 + i;
#pragma unroll
                    for (int j = 0; j < 4; ++j)
                        gout[m * 2048 + n0 + tx * 4 + j] = acc[i][j];
                }
            }
        } else {
            const int tilesA = m128 * 16 * ks_a;
            for (int tile = bid; tile < tilesA; tile += NB) {
                const int s  = tile % ks_a;
                const int u  = tile / ks_a;
                const int n0 = (u & 15) << 7;
                const int m0 = (u >> 4) << 7;
                const int k0 = s * Ka;

                float acc[2][2][4][4] = {};
                auto af4 = [&](int ml, int kk) -> float4 {
                    int gk = k0 + kk;
                    int m = m0 + ml;
                    if (hasx && gk < Oo) {
                        size_t ix = rbase + (size_t)m * Oo + gk;
                        float4 v = *(const float4*)&g_b2cat[gk];
#pragma unroll
                        for (int sc = 0; sc < KSC; ++sc) {
                            float4 r = *(const float4*)&g_rp[sc][ix];
                            v.x += r.x; v.y += r.y; v.z += r.z; v.w += r.w;
                        }
                        return v;
                    }
                    return *(const float4*)&hR[m * Hh + gk - xoff];
                };
                auto bf4 = [&](int kk, int nl) -> float4 {
                    int gk = k0 + kk;
                    const float* src = (hasx && gk < Oo)
                        ? &g_WihI[gk * 2048 + n0 + nl]
                        : &g_WhhI[(size_t)(gk - xoff) * 2048 + n0 + nl];
                    return *(const float4*)src;
                };
                tile128(acc, Ka, af4, bf4, As, Bs);

                float* __restrict__ gout = g_gp[s];
#pragma unroll
                for (int ih = 0; ih < 2; ++ih)
#pragma unroll
                    for (int i = 0; i < 4; ++i) {
                        int m = m0 + ih * 64 + ty * 4 + i;
                        float* dst = &gout[m * 2048 + n0];
#pragma unroll
                        for (int jh = 0; jh < 2; ++jh)
                            *(float4*)&dst[jh * 64 + tx * 4] =
                                make_float4(acc[ih][jh][i][0], acc[ih][jh][i][1],
                                            acc[ih][jh][i][2], acc[ih][jh][i][3]);
                    }
            }
        }
        gridsync(phase);

        // ---- P1: LSTM combine (sum ks_a partials + bias) ----
        {
            const int total = mt * 64 * Hh;
            for (int e = bid * TPB + tid; e < total; e += NB * TPB) {
                int m = e >> 9, j = e & (Hh - 1);
                if (m < nt) {
                    float4 gs = make_float4(0.f, 0.f, 0.f, 0.f);
                    for (int s = 0; s < ks_a; ++s) {
                        float4 gp = *(const float4*)&g_gp[s][m * 2048 + j * 4];
                        gs.x += gp.x; gs.y += gp.y; gs.z += gp.z; gs.w += gp.w;
                    }
                    float4 bg = *(const float4*)&g_bgI[j * 4];
                    float cn = sigm(gs.y + bg.y) * cR[m * Hh + j] +
                               sigm(gs.x + bg.x) * tanh_f(gs.z + bg.z);
                    float hn = sigm(gs.w + bg.w) * tanh_f(cn);
                    cW[m * Hh + j] = cn;
                    hW[m * Hh + j] = hn;
                    g_hs[((size_t)t * Bsz + m) * Hh + j] = hn;
                }
            }
            gridsync(phase);
        }

        // ---- P2: q partials = h_t @ W12T[:, 0:512], K-split 8 (mac64) ----
        const int Kb = MHh / 8;
        const int tilesB = mt * 8 * 8;
        for (int tile = bid; tile < tilesB; tile += NB) {
            const int s  = tile & 7;
            const int u  = tile >> 3;
            const int n0 = (u & 7) << 6;
            const int m0 = (u >> 3) << 6;
            const int k0 = s * Kb;
            float* __restrict__ qout = g_qp[s];
            float acc[4][4] = {};
            auto af = [&](int ml, int kk) -> float { return hW[(m0 + ml) * Hh + k0 + kk]; };
            auto bf = [&](int kk, int nl) -> float {
                return g_W12T[(size_t)(k0 + kk) * 1024 + n0 + nl];
            };
            mac64(acc, Kb, af, bf, As, Bs);
#pragma unroll
            for (int i = 0; i < 4; ++i) {
                int m = m0 + ty * 4 + i;
#pragma unroll
                for (int j = 0; j < 4; ++j)
                    qout[m * MHh + n0 + tx * 4 + j] = acc[i][j];
            }
        }
        gridsync(phase);

        // ---- P3: p1 partials = tanh(sum q + b12) @ W2T1, K-split 4 (mac64) ----
        const int Kc = MHh / KSC;
        const int tilesC = mt * 2 * KSC;
        for (int tile = bid; tile < tilesC; tile += NB) {
            const int s  = tile % KSC;
            const int u  = tile / KSC;
            const int n0 = (u & 1) << 6;
            const int m0 = (u >> 1) << 6;
            const int k0 = s * Kc;
            float* __restrict__ rout = g_rp[s] + (size_t)t * Bsz * Oo;
            float acc[4][4] = {};
            auto af = [&](int ml, int kk) -> float {
                int k = k0 + kk;
                float v = g_b12[k];
#pragma unroll
                for (int s2 = 0; s2 < 8; ++s2) v += g_qp[s2][(m0 + ml) * MHh + k];
                return tanh_f(v);
            };
            auto bf = [&](int kk, int nl) -> float { return g_W2T1[(k0 + kk) * Oo + n0 + nl]; };
            mac64(acc, Kc, af, bf, As, Bs);
#pragma unroll
            for (int i = 0; i < 4; ++i) {
                int m = m0 + ty * 4 + i;
#pragma unroll
                for (int j = 0; j < 4; ++j)
                    rout[(size_t)m * Oo + n0 + tx * 4 + j] = acc[i][j];
            }
        }
        gridsync(phase);
    }
}

// ---------------- final stage ----------------
__global__ void offsets_kernel(const float* __restrict__ offW2, const float* __restrict__ offb2,
                               float* __restrict__ out_off, int Np) {
    int warp = (blockIdx.x * blockDim.x + threadIdx.x) >> 5;
    int lane = threadIdx.x & 31;
    if (warp >= Np) return;
    const float* row = g_buf + (size_t)warp * MHh;
    float s = 0.f;
#pragma unroll
    for (int k = lane; k < MHh; k += 32) s += row[k] * offW2[k];
#pragma unroll
    for (int o = 16; o; o >>= 1) s += __shfl_xor_sync(0xFFFFFFFFu, s, o);
    if (lane == 0) out_off[warp] = s + offb2[0];
}

__global__ void gather_out(const int* __restrict__ pack_idx, float* __restrict__ out, int Np) {
    int gid = blockIdx.x * blockDim.x + threadIdx.x;
    if (gid >= Np * Oo) return;
    int i = gid >> 7, o = gid & 127;
    size_t p = (size_t)pack_idx[i];
    float v1 = g_b2cat[o];
#pragma unroll
    for (int s = 0; s < KSC; ++s) v1 += g_rp[s][p * Oo + o];
    size_t NO = (size_t)Np * Oo;
    out[(size_t)i * Oo + o] = v1;                 // flat_p1
    out[2 * NO + Np + (size_t)i * Oo + o] = v1;   // flat_out (== flat_p1)
}

// ---------------- host ----------------
static float* gsymf(const void* symbol) {
    void* p = nullptr;
    cudaGetSymbolAddress(&p, symbol);
    return (float*)p;
}

extern "C" void kernel_launch(void* const* d_in, const int* in_sizes, int n_in,
                              void* d_out, int out_size) {
    const float* features = (const float*)d_in[0];
    const float* W_f2h    = (const float*)d_in[1];
    const float* b_f2h    = (const float*)d_in[2];
    const float* W_ih     = (const float*)d_in[3];
    const float* W_hh     = (const float*)d_in[4];
    const float* b_ih     = (const float*)d_in[5];
    const float* b_hh     = (const float*)d_in[6];
    const float* p1_W1    = (const float*)d_in[7];
    const float* p1_b1    = (const float*)d_in[8];
    const float* p1_W2    = (const float*)d_in[9];
    const float* p1_b2    = (const float*)d_in[10];
    const float* p2_W1    = (const float*)d_in[11];
    const float* p2_b1    = (const float*)d_in[12];
    const float* p2_W2    = (const float*)d_in[13];
    const float* p2_b2    = (const float*)d_in[14];
    const float* off_W1   = (const float*)d_in[15];
    const float* off_b1   = (const float*)d_in[16];
    const float* off_W2   = (const float*)d_in[17];
    const float* off_b2   = (const float*)d_in[18];
    const int*   lengths  = (const int*)d_in[19];
    const int*   pack_idx = (const int*)d_in[20];
    float* out = (float*)d_out;
    const int Np = in_sizes[20];
    const size_t NO = (size_t)Np * Oo;
    const unsigned mT = (unsigned)((Np + 127) / 128);

    float* p_Wf2hT  = gsymf(g_Wf2hT);
    float* p_bhc    = gsymf(g_bhc);
    float* p_W12T   = gsymf(g_W12T);
    float* p_b12    = gsymf(g_b12);
    float* p_W2T2   = gsymf(g_W2T2);
    float* p_b2cat  = gsymf(g_b2cat);
    float* p_offW1T = gsymf(g_offW1T);
    float* p_hs     = gsymf(g_hs);
    float* p_buf    = gsymf(g_buf);

    auto blocks = [](long long n) { return (unsigned)((n + 255) / 256); };

    // launch 1-2: prep ; launch 3: init GEMM ; launch 4: the scan
    k_prepA<<<blocks(4LL * Hh * Hh), TPB>>>(W_ih, W_hh, b_ih, b_hh, W_f2h, b_f2h);
    k_prepB<<<blocks((long long)Hh * 2 * MHh), TPB>>>(p1_W1, p2_W1, p1_b1, p2_b1,
                                                      p1_W2, p2_W2, p1_b2, p2_b2,
                                                      off_W1, lengths);
    gemmG<2><<<dim3(8, 2), TPB>>>(features, Ff, nullptr, p_Wf2hT, 2 * Hh, p_bhc,
                                  nullptr, Bsz, 2 * Hh, Ff);
    persistent_scan<<<NB, TPB>>>();

    // post-loop over packed rows
    gemmG<1><<<dim3(4, mT), TPB>>>(p_hs, Hh, pack_idx, p_offW1T, MHh, off_b1,
                                   p_buf, Np, MHh, Hh);
    offsets_kernel<<<(Np + 7) / 8, TPB>>>(off_W2, off_b2, out + 2 * NO, Np);

    gemmG<1><<<dim3(4, mT), TPB>>>(p_hs, Hh, pack_idx, p_W12T + MHh, 2 * MHh, p_b12 + MHh,
                                   p_buf, Np, MHh, Hh);
    gemmG<0><<<dim3(1, mT), TPB>>>(p_buf, MHh, nullptr, p_W2T2, Oo, p_b2cat + Oo,
                                   out + NO, Np, Oo, MHh);

    gather_out<<<blocks((long long)Np * Oo), TPB>>>(pack_idx, out, Np);
}